// round 2
// baseline (speedup 1.0000x reference)
#include <cuda_runtime.h>
#include <math.h>

#define N    2048
#define DIN  256
#define DK   64
#define DV   64
#define DR   64
#define PCOLS 256   // DK+DK+DV+DR

#define RPB  4      // rows of output per block in attention kernel
#define TPB  256

// scratch: projection buffer (2 MB) — __device__ global, no allocation
__device__ float g_proj[N * PCOLS];

__device__ __forceinline__ float dot4(float4 a, float4 b) {
    return a.x * b.x + a.y * b.y + a.z * b.z + a.w * b.w;
}

// ---------------------------------------------------------------------------
// Kernel 1: proj = H @ W^T   (H: N x DIN row-major, W: PCOLS x DIN row-major)
// Classic 16x16 smem-tiled GEMM-NT. ~0.27 GFLOP — a few microseconds.
// ---------------------------------------------------------------------------
__global__ void proj_kernel(const float* __restrict__ H,
                            const float* __restrict__ W) {
    __shared__ float Hs[16][17];
    __shared__ float Ws[16][17];
    const int row = blockIdx.y * 16 + threadIdx.y;   // output row (0..N)
    const int colBase = blockIdx.x * 16;             // output col tile

    float acc = 0.f;
    for (int k0 = 0; k0 < DIN; k0 += 16) {
        Hs[threadIdx.y][threadIdx.x] = H[row * DIN + k0 + threadIdx.x];
        Ws[threadIdx.y][threadIdx.x] = W[(colBase + threadIdx.y) * DIN + k0 + threadIdx.x];
        __syncthreads();
#pragma unroll
        for (int kk = 0; kk < 16; kk++)
            acc += Hs[threadIdx.y][kk] * Ws[threadIdx.x][kk];
        __syncthreads();
    }
    g_proj[row * PCOLS + colBase + threadIdx.x] = acc;
}

// ---------------------------------------------------------------------------
// Kernel 2: fused attention, RPB output rows per block.
//   w[r][j] = scale * (Q[i0+r].K[j] + R[i0+r].D[i0+r, j]); softmax; out = p@V
//
// Phase 1 is warp-cooperative: a warp covers 2 adjacent j per step; lanes
// 0-15 hold float4 slices of row j0, lanes 16-31 of j1. All D traffic is
// 512B-contiguous per warp LDG -> 128B/wavefront at L1tex, DRAM-coalesced.
// Dots close with a 4-round shfl_xor butterfly inside each 16-lane group.
// ---------------------------------------------------------------------------
__global__ void __launch_bounds__(TPB)
attn_kernel(const float* __restrict__ D, float* __restrict__ out) {
    __shared__ float w[RPB][N];       // 32 KB: scores -> probs in place
    __shared__ float red[TPB];
    __shared__ float inv_sum[RPB];

    const int tid  = threadIdx.x;
    const int wid  = tid >> 5;
    const int lane = tid & 31;
    const int sub  = lane & 15;       // float4 slot within a 64-float row
    const int half = lane >> 4;       // 0 -> j0, 1 -> j1
    const int i0   = blockIdx.x * RPB;

    const float scale = rsqrtf((float)(DK + DR));

    // Per-lane register slices of Q and R for the RPB rows (L2-resident proj)
    float4 q_reg[RPB], r_reg[RPB];
#pragma unroll
    for (int r = 0; r < RPB; r++) {
        const float* prow = g_proj + (size_t)(i0 + r) * PCOLS;
        q_reg[r] = *(const float4*)(prow + sub * 4);            // Q
        r_reg[r] = *(const float4*)(prow + 192 + sub * 4);      // R
    }

    // ---- phase 1: scores ----
    for (int jb = wid * 2; jb < N; jb += 16) {                  // 8 warps * 2 j
        const int j = jb + half;
        const float4 k4 = *(const float4*)(g_proj + (size_t)j * PCOLS + 64 + sub * 4);

        float acc[RPB];
#pragma unroll
        for (int r = 0; r < RPB; r++) {
            const float4 d4 = *(const float4*)(D + ((size_t)(i0 + r) * N + j) * DR + sub * 4);
            acc[r] = dot4(q_reg[r], k4) + dot4(r_reg[r], d4);
        }
        // reduce within each 16-lane group
#pragma unroll
        for (int o = 1; o < 16; o <<= 1) {
#pragma unroll
            for (int r = 0; r < RPB; r++)
                acc[r] += __shfl_xor_sync(0xFFFFFFFFu, acc[r], o);
        }
        if (sub == 0) {
#pragma unroll
            for (int r = 0; r < RPB; r++)
                w[r][j] = acc[r] * scale;
        }
    }
    __syncthreads();

    // ---- phase 2: softmax, one warp per row ----
    if (wid < RPB) {
        float m = -1e30f;
        for (int j = lane; j < N; j += 32) m = fmaxf(m, w[wid][j]);
#pragma unroll
        for (int o = 16; o > 0; o >>= 1) m = fmaxf(m, __shfl_xor_sync(0xFFFFFFFFu, m, o));
        float s = 0.f;
        for (int j = lane; j < N; j += 32) {
            const float p = __expf(w[wid][j] - m);
            w[wid][j] = p;
            s += p;
        }
#pragma unroll
        for (int o = 16; o > 0; o >>= 1) s += __shfl_xor_sync(0xFFFFFFFFu, s, o);
        if (lane == 0) inv_sum[wid] = 1.f / s;
    }
    __syncthreads();

    // ---- phase 3: out[i_r] = sum_j p[r][j] * V[j] ----
    const int d = tid & 63;        // output dim
    const int g = tid >> 6;        // j-group 0..3
    float acc[RPB];
#pragma unroll
    for (int r = 0; r < RPB; r++) acc[r] = 0.f;

    for (int j = g; j < N; j += 4) {
        const float v = g_proj[(size_t)j * PCOLS + 128 + d];   // V[j][d], coalesced
#pragma unroll
        for (int r = 0; r < RPB; r++) acc[r] += w[r][j] * v;   // smem broadcast
    }

#pragma unroll
    for (int r = 0; r < RPB; r++) {
        red[tid] = acc[r];
        __syncthreads();
        if (g == 0) {
            out[(size_t)(i0 + r) * DV + d] =
                (red[d] + red[64 + d] + red[128 + d] + red[192 + d]) * inv_sum[r];
        }
        __syncthreads();
    }
}

// ---------------------------------------------------------------------------
extern "C" void kernel_launch(void* const* d_in, const int* in_sizes, int n_in,
                              void* d_out, int out_size) {
    const float* H = (const float*)d_in[0];   // (N, DIN)
    const float* D = (const float*)d_in[1];   // (N, N, DR)
    const float* W = (const float*)d_in[2];   // (PCOLS, DIN)
    float* out = (float*)d_out;               // (N, DV)

    dim3 gb(PCOLS / 16, N / 16);
    dim3 tb(16, 16);
    proj_kernel<<<gb, tb>>>(H, W);

    attn_kernel<<<N / RPB, TPB>>>(D, out);
}